// round 1
// baseline (speedup 1.0000x reference)
#include <cuda_runtime.h>
#include <cuda_bf16.h>

// LSTM autoencoder: B independent sequences.
//   LSTM1(in=1, units=10, act=relu, rec_act=sigmoid) over T=50
//   RepeatVector(3) -> LSTM2(10->10) -> Dense(10->1) per step.
// One thread = one batch element. Gates processed as packed f32x2 pairs
// using Blackwell fma.rn.f32x2 (2 fp32 FMA per instruction).

#define UNITS 10
#define TIN   50
#define TOUT  3
#define BLK   128

typedef unsigned long long ull;

__device__ __forceinline__ ull fma2(ull a, ull b, ull c) {
    ull d;
    asm("fma.rn.f32x2 %0, %1, %2, %3;" : "=l"(d) : "l"(a), "l"(b), "l"(c));
    return d;
}
__device__ __forceinline__ ull pack2(float x) {
    ull d;
    asm("mov.b64 %0, {%1, %1};" : "=l"(d) : "f"(x));
    return d;
}
__device__ __forceinline__ float2 unpack2(ull v) {
    float2 r;
    asm("mov.b64 {%0, %1}, %2;" : "=f"(r.x), "=f"(r.y) : "l"(v));
    return r;
}
// sigmoid(x) = 1 / (1 + 2^(-x*log2(e)))  -- 2 MUFU ops (ex2 + rcp), ~ulp accurate
__device__ __forceinline__ float sigmoidf_(float x) {
    float e, r;
    asm("ex2.approx.f32 %0, %1;" : "=f"(e) : "f"(x * -1.4426950408889634f));
    asm("rcp.approx.f32 %0, %1;" : "=f"(r) : "f"(e + 1.0f));
    return r;
}

// Recurrent accumulation: z[0..19] (packed pairs of gates) += h @ R  (R: [10][40])
__device__ __forceinline__ void recur_acc(const float* __restrict__ sR,
                                          ull (&z)[20], const float (&h)[UNITS]) {
#pragma unroll
    for (int k = 0; k < UNITS; k++) {
        ull hh = pack2(h[k]);
        const ulonglong2* Rv = (const ulonglong2*)(sR + k * 40);
#pragma unroll
        for (int j = 0; j < 10; j++) {
            ulonglong2 w = Rv[j];            // LDS.128 broadcast: gates 4j..4j+3
            z[2 * j]     = fma2(hh, w.x, z[2 * j]);
            z[2 * j + 1] = fma2(hh, w.y, z[2 * j + 1]);
        }
    }
}

// Gate math. z pair p holds gates (2p, 2p+1). Gate order: i[0:10) f[10:20) g[20:30) o[30:40)
__device__ __forceinline__ void apply_gates(const ull (&z)[20],
                                            float (&h)[UNITS], float (&c)[UNITS]) {
#pragma unroll
    for (int p = 0; p < 5; p++) {
        float2 zi = unpack2(z[p]);
        float2 zf = unpack2(z[5 + p]);
        float2 zg = unpack2(z[10 + p]);
        float2 zo = unpack2(z[15 + p]);
        int u = 2 * p;
        {
            float iu = sigmoidf_(zi.x), fu = sigmoidf_(zf.x);
            float gu = fmaxf(zg.x, 0.0f), ou = sigmoidf_(zo.x);
            c[u] = fu * c[u] + iu * gu;
            h[u] = ou * fmaxf(c[u], 0.0f);
        }
        {
            float iu = sigmoidf_(zi.y), fu = sigmoidf_(zf.y);
            float gu = fmaxf(zg.y, 0.0f), ou = sigmoidf_(zo.y);
            c[u + 1] = fu * c[u + 1] + iu * gu;
            h[u + 1] = ou * fmaxf(c[u + 1], 0.0f);
        }
    }
}

__global__ __launch_bounds__(BLK) void lstm_ae_kernel(
    const float* __restrict__ inputs,
    const float* __restrict__ W1, const float* __restrict__ R1, const float* __restrict__ b1,
    const float* __restrict__ W2, const float* __restrict__ R2, const float* __restrict__ b2,
    const float* __restrict__ Wd, const float* __restrict__ bd,
    float* __restrict__ out, int B)
{
    __shared__ float xs[TIN * (BLK + 1)];                    // transposed input tile
    __shared__ __align__(16) float sR1[400];
    __shared__ __align__(16) float sW1[40];
    __shared__ __align__(16) float sb1[40];
    __shared__ __align__(16) float sW2[400];
    __shared__ __align__(16) float sR2[400];
    __shared__ __align__(16) float sb2[40];
    __shared__ float sWd[11];

    const int tid  = threadIdx.x;
    const int base = blockIdx.x * BLK;

    // --- load weights into shared ---
    for (int i = tid; i < 400; i += BLK) {
        sR1[i] = R1[i];
        sR2[i] = R2[i];
        sW2[i] = W2[i];
    }
    if (tid < 40) {
        sW1[tid] = W1[tid];
        sb1[tid] = b1[tid];
        sb2[tid] = b2[tid];
    }
    if (tid < UNITS) sWd[tid] = Wd[tid];
    if (tid == 0)    sWd[UNITS] = bd[0];

    // --- stage inputs, transposing [elem][t] -> [t][elem] for conflict-free reads ---
    const long gbase  = (long)base * TIN;
    const long total  = (long)B * TIN;
    for (int idx = tid; idx < BLK * TIN; idx += BLK) {
        int e = idx / TIN;
        int t = idx - e * TIN;
        long g = gbase + idx;                                // contiguous global read
        xs[t * (BLK + 1) + e] = (g < total) ? inputs[g] : 0.0f;
    }
    __syncthreads();

    float h[UNITS], c[UNITS];
#pragma unroll
    for (int u = 0; u < UNITS; u++) { h[u] = 0.0f; c[u] = 0.0f; }

    ull z[20];
    const ulonglong2* W1v = (const ulonglong2*)sW1;
    const ulonglong2* b1v = (const ulonglong2*)sb1;

    // ================= LSTM 1 over 50 steps =================
    for (int t = 0; t < TIN; t++) {
        float x  = xs[t * (BLK + 1) + tid];
        ull   xx = pack2(x);
#pragma unroll
        for (int j = 0; j < 10; j++) {
            ulonglong2 w  = W1v[j];
            ulonglong2 bb = b1v[j];
            z[2 * j]     = fma2(xx, w.x, bb.x);
            z[2 * j + 1] = fma2(xx, w.y, bb.y);
        }
        recur_acc(sR1, z, h);
        apply_gates(z, h, c);
    }

    // ================= LSTM 2: input is constant h1, hoist h1@W2 + b2 =================
    ull xz[20];
    {
        const ulonglong2* b2v = (const ulonglong2*)sb2;
#pragma unroll
        for (int j = 0; j < 10; j++) {
            ulonglong2 bb = b2v[j];
            xz[2 * j]     = bb.x;
            xz[2 * j + 1] = bb.y;
        }
#pragma unroll
        for (int k = 0; k < UNITS; k++) {
            ull hh = pack2(h[k]);
            const ulonglong2* Wv = (const ulonglong2*)(sW2 + k * 40);
#pragma unroll
            for (int j = 0; j < 10; j++) {
                ulonglong2 w = Wv[j];
                xz[2 * j]     = fma2(hh, w.x, xz[2 * j]);
                xz[2 * j + 1] = fma2(hh, w.y, xz[2 * j + 1]);
            }
        }
    }

#pragma unroll
    for (int u = 0; u < UNITS; u++) { h[u] = 0.0f; c[u] = 0.0f; }

    const int  elem  = base + tid;
    const bool valid = elem < B;

#pragma unroll
    for (int s = 0; s < TOUT; s++) {
#pragma unroll
        for (int j = 0; j < 20; j++) z[j] = xz[j];
        recur_acc(sR2, z, h);
        apply_gates(z, h, c);
        float acc = sWd[UNITS];
#pragma unroll
        for (int u = 0; u < UNITS; u++) acc = fmaf(h[u], sWd[u], acc);
        if (valid) out[(long)elem * TOUT + s] = acc;
    }
}

extern "C" void kernel_launch(void* const* d_in, const int* in_sizes, int n_in,
                              void* d_out, int out_size) {
    const float* inputs = (const float*)d_in[0];
    const float* W1     = (const float*)d_in[1];
    const float* R1     = (const float*)d_in[2];
    const float* b1     = (const float*)d_in[3];
    const float* W2     = (const float*)d_in[4];
    const float* R2     = (const float*)d_in[5];
    const float* b2     = (const float*)d_in[6];
    const float* Wd     = (const float*)d_in[7];
    const float* bd     = (const float*)d_in[8];
    float* out = (float*)d_out;

    int B = in_sizes[0] / TIN;
    int grid = (B + BLK - 1) / BLK;
    lstm_ae_kernel<<<grid, BLK>>>(inputs, W1, R1, b1, W2, R2, b2, Wd, bd, out, B);
}